// round 16
// baseline (speedup 1.0000x reference)
#include <cuda_runtime.h>
#include <cstdint>
#include <math.h>

#define B    32
#define NIN  512
#define DIN  64
#define NOUT 32
#define DOUT 64
#define MD   (NOUT*DOUT)   // 2048

// d_out layout (fp32, tuple concat order)
#define OFF_CAP 0
#define OFF_ACT 65536
#define OFF_QK  66560
#define OFF_EMB 590848

#define NCHUNK_V 7     // 74 n-chunks -> 4*74 = 296 blocks = 148 SM * 2 CTA
#define PROW 36        // pose smem row stride (floats), 16B-aligned rows
#define PS_FLOATS (NCHUNK_V * DIN * PROW)        // 16128 floats = 64512 B
#define ABLK 8                                   // a's per cp.async stage block
#define WBUF_FLOATS (ABLK * 512)                 // 4096 floats = 16 KB
#define NSTAGE 3
#define SMEM_V ((PS_FLOATS + NSTAGE * WBUF_FLOATS) * 4)   // 113664 B

typedef unsigned long long u64;
typedef unsigned int u32;

__device__ float g_cap[3][B * MD];

#define CP_ASYNC16(dst, src) \
    asm volatile("cp.async.ca.shared.global [%0], [%1], 16;\n" :: "r"(dst), "l"(src))
#define CP_COMMIT() asm volatile("cp.async.commit_group;\n" ::: "memory")
#define CP_WAIT2()  asm volatile("cp.async.wait_group 2;\n" ::: "memory")

// ---------------------------------------------------------------------------
__global__ void zero_kernel(float4* __restrict__ p)
{
    p[blockIdx.x * blockDim.x + threadIdx.x] = make_float4(0.f, 0.f, 0.f, 0.f);
}

// ---------------------------------------------------------------------------
// Kernel 1: votes[b,n,m,d] = sum_a pose[b,n,a] * W[n,a,m,d]
// R15 body with a 3-stage cp.async W pipeline (prefetch distance 2 blocks).
// Thread tile 8b x 8md (chunked: mdg*4 and mdg*4+256), f32x2 accumulators.
// ---------------------------------------------------------------------------
__global__ __launch_bounds__(256, 2) void votes_kernel(
    const float* __restrict__ pose, const float* __restrict__ W,
    float* __restrict__ votes)
{
    int mdt = blockIdx.x;          // 0..3
    int nc  = blockIdx.y;          // 0..73
    int t   = threadIdx.x;         // 0..255
    int bg  = t >> 6;              // 0..3   : b-group (8 b's)
    int mdg = t & 63;              // 0..63
    int md0 = mdt * 512 + mdg * 4; // chunk 0; chunk 1 = +256

    extern __shared__ float smem_all[];
    float* ps   = smem_all;                  // [NCHUNK_V][DIN][PROW]
    float* wbuf = smem_all + PS_FLOATS;      // [NSTAGE][WBUF_FLOATS]
    u32 wb_addr = (u32)__cvta_generic_to_shared(wbuf);

    int n0  = nc * NCHUNK_V;
    int cnt = (n0 + NCHUNK_V <= NIN) ? NCHUNK_V : (NIN - n0);
    int total_blk = cnt * ABLK;    // 8 a-blocks per n

    const float* Wbase = W + (size_t)mdt * 512;

    // kick off prefetch of W a-blocks 0,1,2 first (overlaps pose staging)
    #pragma unroll
    for (int s = 0; s < NSTAGE; ++s) {
        if (s < total_blk) {
            const float* src_base = Wbase +
                ((size_t)(n0 + (s >> 3)) * DIN + (s & 7) * 8) * MD;
            u32 dstp = wb_addr + (u32)s * (WBUF_FLOATS * 4);
            #pragma unroll
            for (int i = 0; i < 4; ++i) {
                int f = t + i * 256;            // float4 index, 0..1023
                int arow = f >> 7;
                int col4 = f & 127;
                CP_ASYNC16(dstp + f * 16, src_base + (size_t)arow * MD + col4 * 4);
            }
        }
        CP_COMMIT();
    }

    // stage pose for the whole chunk
    {
        int sb  = t >> 3;
        int sa0 = (t & 7) * 8;
        for (int it = 0; it < cnt; ++it) {
            const float* pp = pose + ((size_t)sb * NIN + n0 + it) * DIN + sa0;
            float4 p0 = *(const float4*)pp;
            float4 p1 = *(const float4*)(pp + 4);
            float* dst = ps + (it * DIN + sa0) * PROW + sb;
            dst[0 * PROW] = p0.x; dst[1 * PROW] = p0.y;
            dst[2 * PROW] = p0.z; dst[3 * PROW] = p0.w;
            dst[4 * PROW] = p1.x; dst[5 * PROW] = p1.y;
            dst[6 * PROW] = p1.z; dst[7 * PROW] = p1.w;
        }
    }

    int cur = 0;   // note: (g+NSTAGE) % NSTAGE == g % NSTAGE == cur
    for (int nl = 0; nl < cnt; ++nl) {
        int n = n0 + nl;

        u64 acc[8][4];   // [bb][c0.lo, c0.hi, c1.lo, c1.hi]
        #pragma unroll
        for (int bb = 0; bb < 8; ++bb)
            #pragma unroll
            for (int p = 0; p < 4; ++p) acc[bb][p] = 0ull;

        const float* pr = ps + nl * DIN * PROW + bg * 8;

        for (int kb = 0; kb < ABLK; ++kb) {
            int g = nl * ABLK + kb;

            CP_WAIT2();          // a-block g resident (2 newest groups may be in flight)
            __syncthreads();

            const float* wc = wbuf + cur * WBUF_FLOATS + mdg * 4;
            #pragma unroll
            for (int al = 0; al < ABLK; ++al) {
                int a = kb * ABLK + al;
                ulonglong2 w0 = *(const ulonglong2*)(wc + al * 512);        // md0..+3
                ulonglong2 w1 = *(const ulonglong2*)(wc + al * 512 + 256);  // +256
                const float* pa = pr + a * PROW;
                #pragma unroll
                for (int bb = 0; bb < 8; bb += 4) {
                    float4 pv = *(const float4*)(pa + bb);   // broadcast LDS.128
                    u64 q0, q1, q2, q3;
                    asm("mov.b64 %0, {%1, %1};" : "=l"(q0) : "r"(__float_as_uint(pv.x)));
                    asm("mov.b64 %0, {%1, %1};" : "=l"(q1) : "r"(__float_as_uint(pv.y)));
                    asm("mov.b64 %0, {%1, %1};" : "=l"(q2) : "r"(__float_as_uint(pv.z)));
                    asm("mov.b64 %0, {%1, %1};" : "=l"(q3) : "r"(__float_as_uint(pv.w)));
                    asm("fma.rn.f32x2 %0, %1, %2, %0;" : "+l"(acc[bb+0][0]) : "l"(w0.x), "l"(q0));
                    asm("fma.rn.f32x2 %0, %1, %2, %0;" : "+l"(acc[bb+0][1]) : "l"(w0.y), "l"(q0));
                    asm("fma.rn.f32x2 %0, %1, %2, %0;" : "+l"(acc[bb+0][2]) : "l"(w1.x), "l"(q0));
                    asm("fma.rn.f32x2 %0, %1, %2, %0;" : "+l"(acc[bb+0][3]) : "l"(w1.y), "l"(q0));
                    asm("fma.rn.f32x2 %0, %1, %2, %0;" : "+l"(acc[bb+1][0]) : "l"(w0.x), "l"(q1));
                    asm("fma.rn.f32x2 %0, %1, %2, %0;" : "+l"(acc[bb+1][1]) : "l"(w0.y), "l"(q1));
                    asm("fma.rn.f32x2 %0, %1, %2, %0;" : "+l"(acc[bb+1][2]) : "l"(w1.x), "l"(q1));
                    asm("fma.rn.f32x2 %0, %1, %2, %0;" : "+l"(acc[bb+1][3]) : "l"(w1.y), "l"(q1));
                    asm("fma.rn.f32x2 %0, %1, %2, %0;" : "+l"(acc[bb+2][0]) : "l"(w0.x), "l"(q2));
                    asm("fma.rn.f32x2 %0, %1, %2, %0;" : "+l"(acc[bb+2][1]) : "l"(w0.y), "l"(q2));
                    asm("fma.rn.f32x2 %0, %1, %2, %0;" : "+l"(acc[bb+2][2]) : "l"(w1.x), "l"(q2));
                    asm("fma.rn.f32x2 %0, %1, %2, %0;" : "+l"(acc[bb+2][3]) : "l"(w1.y), "l"(q2));
                    asm("fma.rn.f32x2 %0, %1, %2, %0;" : "+l"(acc[bb+3][0]) : "l"(w0.x), "l"(q3));
                    asm("fma.rn.f32x2 %0, %1, %2, %0;" : "+l"(acc[bb+3][1]) : "l"(w0.y), "l"(q3));
                    asm("fma.rn.f32x2 %0, %1, %2, %0;" : "+l"(acc[bb+3][2]) : "l"(w1.x), "l"(q3));
                    asm("fma.rn.f32x2 %0, %1, %2, %0;" : "+l"(acc[bb+3][3]) : "l"(w1.y), "l"(q3));
                }
            }
            __syncthreads();   // buffer `cur` fully consumed

            // prefetch a-block g+NSTAGE into the buffer just freed (same index)
            if (g + NSTAGE < total_blk) {
                int gn = g + NSTAGE;
                const float* src_base = Wbase +
                    ((size_t)(n0 + (gn >> 3)) * DIN + (gn & 7) * 8) * MD;
                u32 dstp = wb_addr + (u32)cur * (WBUF_FLOATS * 4);
                #pragma unroll
                for (int i = 0; i < 4; ++i) {
                    int f = t + i * 256;
                    int arow = f >> 7;
                    int col4 = f & 127;
                    CP_ASYNC16(dstp + f * 16, src_base + (size_t)arow * MD + col4 * 4);
                }
            }
            CP_COMMIT();       // commit every iteration to keep group counting exact
            cur = (cur == NSTAGE - 1) ? 0 : cur + 1;
        }

        #pragma unroll
        for (int bb = 0; bb < 8; ++bb) {
            int b = bg * 8 + bb;
            float* vb = votes + ((size_t)b * NIN + n) * MD + md0;
            *(ulonglong2*)vb         = make_ulonglong2(acc[bb][0], acc[bb][1]);
            *(ulonglong2*)(vb + 256) = make_ulonglong2(acc[bb][2], acc[bb][3]);
        }
    }
}

// ---------------------------------------------------------------------------
// Kernel 2: cap0[b,md] += sum_{n quarter} votes[b,n,md] / NOUT (pre-zeroed)
// grid (8 md-tiles, 32 b, 4 n-quarters) = 1024 blocks.
// ---------------------------------------------------------------------------
__global__ __launch_bounds__(256) void cap0_kernel(
    const float* __restrict__ votes, float* __restrict__ cap)
{
    int b  = blockIdx.y;
    int md = blockIdx.x * 256 + threadIdx.x;
    int nh = blockIdx.z << 7;      // 0,128,256,384
    const float* v = votes + ((size_t)b * NIN + nh) * MD + md;
    float s = 0.f;
    #pragma unroll 16
    for (int n = 0; n < 128; ++n) s += v[(size_t)n * MD];
    atomicAdd(&cap[b * MD + md], s * (1.0f / NOUT));
}

// ---------------------------------------------------------------------------
// Kernel 3: one routing iteration (R5-proven, unchanged, at BW ceiling).
// ---------------------------------------------------------------------------
__global__ __launch_bounds__(256, 3) void route_kernel(
    float* __restrict__ votes, const float* __restrict__ act,
    const float* __restrict__ cap_in, float* __restrict__ cap_out,
    float* __restrict__ qk_out, int final_flag)
{
    int b   = blockIdx.y;
    int n0  = blockIdx.x * 32;
    int tid = threadIdx.x;
    int m   = tid >> 3;
    int j   = tid & 7;

    __shared__ float lg[NOUT];
    __shared__ float qa_s[NOUT];

    float capr[8];
    {
        const float* cp = cap_in + ((size_t)(b * NOUT + m)) * DOUT + j * 8;
        *(float4*)&capr[0] = *(const float4*)cp;
        *(float4*)&capr[4] = *(const float4*)(cp + 4);
    }

    float acc[8];
    #pragma unroll
    for (int k = 0; k < 8; ++k) acc[k] = 0.f;

    float* base = votes + (((size_t)b * NIN + n0) * NOUT + m) * DOUT + j * 8;

    float4 cur0 = *(const float4*)base;
    float4 cur1 = *(const float4*)(base + 4);

    #pragma unroll 1
    for (int nn = 0; nn < 32; ++nn) {
        int nn2 = (nn < 31) ? nn + 1 : nn;
        const float* np = base + (size_t)nn2 * MD;
        float4 nxt0 = *(const float4*)np;
        float4 nxt1 = *(const float4*)(np + 4);

        float p = cur0.x * capr[0] + cur0.y * capr[1] + cur0.z * capr[2] + cur0.w * capr[3]
                + cur1.x * capr[4] + cur1.y * capr[5] + cur1.z * capr[6] + cur1.w * capr[7];
        p += __shfl_xor_sync(0xffffffffu, p, 1);
        p += __shfl_xor_sync(0xffffffffu, p, 2);
        p += __shfl_xor_sync(0xffffffffu, p, 4);
        if (j == 0) lg[m] = p * 0.125f;
        __syncthreads();

        if (tid < 32) {
            float x  = lg[tid];
            float mx = x;
            #pragma unroll
            for (int o = 16; o; o >>= 1)
                mx = fmaxf(mx, __shfl_xor_sync(0xffffffffu, mx, o));
            float e = __expf(x - mx);
            float s = e;
            #pragma unroll
            for (int o = 16; o; o >>= 1)
                s += __shfl_xor_sync(0xffffffffu, s, o);
            float q = e / s;
            qa_s[tid] = q * __ldg(&act[b * NIN + n0 + nn]);
            if (final_flag)
                qk_out[((size_t)b * NIN + n0 + nn) * NOUT + tid] = q;
        }
        __syncthreads();

        float wa = qa_s[m];
        acc[0] = fmaf(wa, cur0.x, acc[0]); acc[1] = fmaf(wa, cur0.y, acc[1]);
        acc[2] = fmaf(wa, cur0.z, acc[2]); acc[3] = fmaf(wa, cur0.w, acc[3]);
        acc[4] = fmaf(wa, cur1.x, acc[4]); acc[5] = fmaf(wa, cur1.y, acc[5]);
        acc[6] = fmaf(wa, cur1.z, acc[6]); acc[7] = fmaf(wa, cur1.w, acc[7]);

        if (final_flag) {
            float* vp = base + (size_t)nn * MD;
            *(float4*)vp       = make_float4(wa * cur0.x, wa * cur0.y, wa * cur0.z, wa * cur0.w);
            *(float4*)(vp + 4) = make_float4(wa * cur1.x, wa * cur1.y, wa * cur1.z, wa * cur1.w);
        }

        cur0 = nxt0; cur1 = nxt1;
    }

    float* co = cap_out + ((size_t)(b * NOUT + m)) * DOUT + j * 8;
    #pragma unroll
    for (int k = 0; k < 8; ++k) atomicAdd(co + k, acc[k]);
}

// ---------------------------------------------------------------------------
__global__ void act_kernel(const float* __restrict__ cap, float* __restrict__ actout)
{
    int i = blockIdx.x * blockDim.x + threadIdx.x;
    if (i < B * NOUT) {
        const float* c = cap + i * DOUT;
        float s = 0.f;
        #pragma unroll
        for (int d = 0; d < DOUT; ++d) s += c[d] * c[d];
        actout[i] = sqrtf(s);
    }
}

// ---------------------------------------------------------------------------
extern "C" void kernel_launch(void* const* d_in, const int* in_sizes, int n_in,
                              void* d_out, int out_size)
{
    const float* pose = (const float*)d_in[0];
    const float* act  = (const float*)d_in[1];
    const float* W    = (const float*)d_in[2];

    float* out = (float*)d_out;
    float* cap = out + OFF_CAP;
    float* qk  = out + OFF_QK;
    float* emb = out + OFF_EMB;

    float* capbuf;
    cudaGetSymbolAddress((void**)&capbuf, g_cap);
    float* cap0 = capbuf;
    float* cap1 = capbuf + B * MD;
    float* cap2 = capbuf + 2 * B * MD;

    cudaFuncSetAttribute(votes_kernel,
                         cudaFuncAttributeMaxDynamicSharedMemorySize, SMEM_V);

    // zeroing split keeps votes at the verified ncu capture slot (#4)
    zero_kernel<<<192, 256>>>((float4*)cap0);
    zero_kernel<<<32, 256>>>((float4*)cap);
    zero_kernel<<<32, 256>>>((float4*)cap + 8192);

    // launch 4: votes (profiled)
    votes_kernel<<<dim3(4, 74), 256, SMEM_V>>>(pose, W, emb);

    cap0_kernel<<<dim3(8, B, 4), 256>>>(emb, cap0);

    route_kernel<<<dim3(16, B), 256>>>(emb, act, cap0, cap1, qk, 0);
    route_kernel<<<dim3(16, B), 256>>>(emb, act, cap1, cap2, qk, 0);
    route_kernel<<<dim3(16, B), 256>>>(emb, act, cap2, cap, qk, 1);

    act_kernel<<<4, 256>>>(cap, out + OFF_ACT);
}

// round 17
// speedup vs baseline: 1.0344x; 1.0344x over previous
#include <cuda_runtime.h>
#include <cstdint>
#include <math.h>

#define B    32
#define NIN  512
#define DIN  64
#define NOUT 32
#define DOUT 64
#define MD   (NOUT*DOUT)   // 2048

// d_out layout (fp32, tuple concat order)
#define OFF_CAP 0
#define OFF_ACT 65536
#define OFF_QK  66560
#define OFF_EMB 590848

#define NCHUNK_V 7     // 74 n-chunks -> 4*74 = 296 blocks = 148 SM * 2 CTA
#define PROW 36        // pose smem row stride (floats), 16B-aligned rows
#define PS_FLOATS (NCHUNK_V * DIN * PROW)        // 16128 floats = 64512 B
#define ABLK 8                                   // a's per cp.async stage block
#define WBUF_FLOATS (ABLK * 512)                 // 4096 floats = 16 KB
#define SMEM_V ((PS_FLOATS + 2 * WBUF_FLOATS) * 4)   // 97280 B

typedef unsigned long long u64;
typedef unsigned int u32;

__device__ float g_cap[3][B * MD];

#define CP_ASYNC16(dst, src) \
    asm volatile("cp.async.ca.shared.global [%0], [%1], 16;\n" :: "r"(dst), "l"(src))
#define CP_COMMIT() asm volatile("cp.async.commit_group;\n" ::: "memory")
#define CP_WAIT1()  asm volatile("cp.async.wait_group 1;\n" ::: "memory")

// ---------------------------------------------------------------------------
// Kernel 0: zero the 3 scratch capsule buffers + d_out cap region (one launch)
// ---------------------------------------------------------------------------
__global__ void zero_kernel(float4* __restrict__ scratch, float4* __restrict__ capout)
{
    int i = blockIdx.x * blockDim.x + threadIdx.x;   // 0 .. 4*16384-1
    if (i < 3 * 16384) scratch[i] = make_float4(0.f, 0.f, 0.f, 0.f);
    else               capout[i - 3 * 16384] = make_float4(0.f, 0.f, 0.f, 0.f);
}

// ---------------------------------------------------------------------------
// Kernel 1: votes[b,n,m,d] = sum_a pose[b,n,a] * W[n,a,m,d]
// R15-proven: cp.async double-buffered W staging (8-a blocks, prefetch issued
// BEFORE the wait). Thread tile 8b x 8md (chunked md0 / md0+256), f32x2 accs.
// ---------------------------------------------------------------------------
__global__ __launch_bounds__(256, 2) void votes_kernel(
    const float* __restrict__ pose, const float* __restrict__ W,
    float* __restrict__ votes)
{
    int mdt = blockIdx.x;          // 0..3
    int nc  = blockIdx.y;          // 0..73
    int t   = threadIdx.x;         // 0..255
    int bg  = t >> 6;              // 0..3   : b-group (8 b's)
    int mdg = t & 63;              // 0..63
    int md0 = mdt * 512 + mdg * 4; // chunk 0; chunk 1 = +256

    extern __shared__ float smem_all[];
    float* ps   = smem_all;                  // [NCHUNK_V][DIN][PROW]
    float* wbuf = smem_all + PS_FLOATS;      // [2][WBUF_FLOATS]
    u32 wb_addr = (u32)__cvta_generic_to_shared(wbuf);

    int n0  = nc * NCHUNK_V;
    int cnt = (n0 + NCHUNK_V <= NIN) ? NCHUNK_V : (NIN - n0);
    int total_blk = cnt * ABLK;    // a-blocks in this chunk (8 per n)

    const float* Wbase = W + (size_t)mdt * 512;

    // stage pose for the whole chunk
    {
        int sb  = t >> 3;
        int sa0 = (t & 7) * 8;
        for (int it = 0; it < cnt; ++it) {
            const float* pp = pose + ((size_t)sb * NIN + n0 + it) * DIN + sa0;
            float4 p0 = *(const float4*)pp;
            float4 p1 = *(const float4*)(pp + 4);
            float* dst = ps + (it * DIN + sa0) * PROW + sb;
            dst[0 * PROW] = p0.x; dst[1 * PROW] = p0.y;
            dst[2 * PROW] = p0.z; dst[3 * PROW] = p0.w;
            dst[4 * PROW] = p1.x; dst[5 * PROW] = p1.y;
            dst[6 * PROW] = p1.z; dst[7 * PROW] = p1.w;
        }
    }

    // prefetch W a-block 0
    {
        const float* src_base = Wbase + (size_t)n0 * DIN * MD;
        #pragma unroll
        for (int i = 0; i < 4; ++i) {
            int f = t + i * 256;            // float4 index, 0..1023
            int arow = f >> 7;              // 0..7
            int col4 = f & 127;
            CP_ASYNC16(wb_addr + f * 16, src_base + (size_t)arow * MD + col4 * 4);
        }
        CP_COMMIT();
    }

    for (int nl = 0; nl < cnt; ++nl) {
        int n = n0 + nl;

        u64 acc[8][4];   // [bb][c0.lo, c0.hi, c1.lo, c1.hi]
        #pragma unroll
        for (int bb = 0; bb < 8; ++bb)
            #pragma unroll
            for (int p = 0; p < 4; ++p) acc[bb][p] = 0ull;

        const float* pr = ps + nl * DIN * PROW + bg * 8;

        for (int kb = 0; kb < ABLK; ++kb) {
            int g = nl * ABLK + kb;

            // prefetch a-block g+1 into the other buffer
            if (g + 1 < total_blk) {
                int gn = g + 1;
                const float* src_base = Wbase +
                    ((size_t)(n0 + (gn >> 3)) * DIN + (gn & 7) * 8) * MD;
                u32 dstp = wb_addr + (u32)(gn & 1) * (WBUF_FLOATS * 4);
                #pragma unroll
                for (int i = 0; i < 4; ++i) {
                    int f = t + i * 256;
                    int arow = f >> 7;
                    int col4 = f & 127;
                    CP_ASYNC16(dstp + f * 16, src_base + (size_t)arow * MD + col4 * 4);
                }
            }
            CP_COMMIT();
            CP_WAIT1();          // a-block g is resident
            __syncthreads();

            const float* wc = wbuf + (g & 1) * WBUF_FLOATS + mdg * 4;
            #pragma unroll
            for (int al = 0; al < ABLK; ++al) {
                int a = kb * ABLK + al;
                ulonglong2 w0 = *(const ulonglong2*)(wc + al * 512);        // md0..+3
                ulonglong2 w1 = *(const ulonglong2*)(wc + al * 512 + 256);  // +256
                const float* pa = pr + a * PROW;
                #pragma unroll
                for (int bb = 0; bb < 8; bb += 4) {
                    float4 pv = *(const float4*)(pa + bb);   // broadcast LDS.128
                    u64 q0, q1, q2, q3;
                    asm("mov.b64 %0, {%1, %1};" : "=l"(q0) : "r"(__float_as_uint(pv.x)));
                    asm("mov.b64 %0, {%1, %1};" : "=l"(q1) : "r"(__float_as_uint(pv.y)));
                    asm("mov.b64 %0, {%1, %1};" : "=l"(q2) : "r"(__float_as_uint(pv.z)));
                    asm("mov.b64 %0, {%1, %1};" : "=l"(q3) : "r"(__float_as_uint(pv.w)));
                    asm("fma.rn.f32x2 %0, %1, %2, %0;" : "+l"(acc[bb+0][0]) : "l"(w0.x), "l"(q0));
                    asm("fma.rn.f32x2 %0, %1, %2, %0;" : "+l"(acc[bb+0][1]) : "l"(w0.y), "l"(q0));
                    asm("fma.rn.f32x2 %0, %1, %2, %0;" : "+l"(acc[bb+0][2]) : "l"(w1.x), "l"(q0));
                    asm("fma.rn.f32x2 %0, %1, %2, %0;" : "+l"(acc[bb+0][3]) : "l"(w1.y), "l"(q0));
                    asm("fma.rn.f32x2 %0, %1, %2, %0;" : "+l"(acc[bb+1][0]) : "l"(w0.x), "l"(q1));
                    asm("fma.rn.f32x2 %0, %1, %2, %0;" : "+l"(acc[bb+1][1]) : "l"(w0.y), "l"(q1));
                    asm("fma.rn.f32x2 %0, %1, %2, %0;" : "+l"(acc[bb+1][2]) : "l"(w1.x), "l"(q1));
                    asm("fma.rn.f32x2 %0, %1, %2, %0;" : "+l"(acc[bb+1][3]) : "l"(w1.y), "l"(q1));
                    asm("fma.rn.f32x2 %0, %1, %2, %0;" : "+l"(acc[bb+2][0]) : "l"(w0.x), "l"(q2));
                    asm("fma.rn.f32x2 %0, %1, %2, %0;" : "+l"(acc[bb+2][1]) : "l"(w0.y), "l"(q2));
                    asm("fma.rn.f32x2 %0, %1, %2, %0;" : "+l"(acc[bb+2][2]) : "l"(w1.x), "l"(q2));
                    asm("fma.rn.f32x2 %0, %1, %2, %0;" : "+l"(acc[bb+2][3]) : "l"(w1.y), "l"(q2));
                    asm("fma.rn.f32x2 %0, %1, %2, %0;" : "+l"(acc[bb+3][0]) : "l"(w0.x), "l"(q3));
                    asm("fma.rn.f32x2 %0, %1, %2, %0;" : "+l"(acc[bb+3][1]) : "l"(w0.y), "l"(q3));
                    asm("fma.rn.f32x2 %0, %1, %2, %0;" : "+l"(acc[bb+3][2]) : "l"(w1.x), "l"(q3));
                    asm("fma.rn.f32x2 %0, %1, %2, %0;" : "+l"(acc[bb+3][3]) : "l"(w1.y), "l"(q3));
                }
            }
            __syncthreads();   // all consumed buf[g&1] before it is re-staged
        }

        #pragma unroll
        for (int bb = 0; bb < 8; ++bb) {
            int b = bg * 8 + bb;
            float* vb = votes + ((size_t)b * NIN + n) * MD + md0;
            *(ulonglong2*)vb         = make_ulonglong2(acc[bb][0], acc[bb][1]);
            *(ulonglong2*)(vb + 256) = make_ulonglong2(acc[bb][2], acc[bb][3]);
        }
    }
}

// ---------------------------------------------------------------------------
// Kernel 2: cap0[b,md] += sum_{n half} votes[b,n,md] / NOUT  (cap0 pre-zeroed)
// ---------------------------------------------------------------------------
__global__ __launch_bounds__(256) void cap0_kernel(
    const float* __restrict__ votes, float* __restrict__ cap)
{
    int b  = blockIdx.y;
    int md = blockIdx.x * 256 + threadIdx.x;
    int nh = blockIdx.z << 8;
    const float* v = votes + ((size_t)b * NIN + nh) * MD + md;
    float s = 0.f;
    #pragma unroll 16
    for (int n = 0; n < 256; ++n) s += v[(size_t)n * MD];
    atomicAdd(&cap[b * MD + md], s * (1.0f / NOUT));
}

// ---------------------------------------------------------------------------
// Kernel 3: one routing iteration (R5-proven, unchanged, at BW ceiling).
// ---------------------------------------------------------------------------
__global__ __launch_bounds__(256, 3) void route_kernel(
    float* __restrict__ votes, const float* __restrict__ act,
    const float* __restrict__ cap_in, float* __restrict__ cap_out,
    float* __restrict__ qk_out, int final_flag)
{
    int b   = blockIdx.y;
    int n0  = blockIdx.x * 32;
    int tid = threadIdx.x;
    int m   = tid >> 3;
    int j   = tid & 7;

    __shared__ float lg[NOUT];
    __shared__ float qa_s[NOUT];

    float capr[8];
    {
        const float* cp = cap_in + ((size_t)(b * NOUT + m)) * DOUT + j * 8;
        *(float4*)&capr[0] = *(const float4*)cp;
        *(float4*)&capr[4] = *(const float4*)(cp + 4);
    }

    float acc[8];
    #pragma unroll
    for (int k = 0; k < 8; ++k) acc[k] = 0.f;

    float* base = votes + (((size_t)b * NIN + n0) * NOUT + m) * DOUT + j * 8;

    float4 cur0 = *(const float4*)base;
    float4 cur1 = *(const float4*)(base + 4);

    #pragma unroll 1
    for (int nn = 0; nn < 32; ++nn) {
        int nn2 = (nn < 31) ? nn + 1 : nn;
        const float* np = base + (size_t)nn2 * MD;
        float4 nxt0 = *(const float4*)np;
        float4 nxt1 = *(const float4*)(np + 4);

        float p = cur0.x * capr[0] + cur0.y * capr[1] + cur0.z * capr[2] + cur0.w * capr[3]
                + cur1.x * capr[4] + cur1.y * capr[5] + cur1.z * capr[6] + cur1.w * capr[7];
        p += __shfl_xor_sync(0xffffffffu, p, 1);
        p += __shfl_xor_sync(0xffffffffu, p, 2);
        p += __shfl_xor_sync(0xffffffffu, p, 4);
        if (j == 0) lg[m] = p * 0.125f;
        __syncthreads();

        if (tid < 32) {
            float x  = lg[tid];
            float mx = x;
            #pragma unroll
            for (int o = 16; o; o >>= 1)
                mx = fmaxf(mx, __shfl_xor_sync(0xffffffffu, mx, o));
            float e = __expf(x - mx);
            float s = e;
            #pragma unroll
            for (int o = 16; o; o >>= 1)
                s += __shfl_xor_sync(0xffffffffu, s, o);
            float q = e / s;
            qa_s[tid] = q * __ldg(&act[b * NIN + n0 + nn]);
            if (final_flag)
                qk_out[((size_t)b * NIN + n0 + nn) * NOUT + tid] = q;
        }
        __syncthreads();

        float wa = qa_s[m];
        acc[0] = fmaf(wa, cur0.x, acc[0]); acc[1] = fmaf(wa, cur0.y, acc[1]);
        acc[2] = fmaf(wa, cur0.z, acc[2]); acc[3] = fmaf(wa, cur0.w, acc[3]);
        acc[4] = fmaf(wa, cur1.x, acc[4]); acc[5] = fmaf(wa, cur1.y, acc[5]);
        acc[6] = fmaf(wa, cur1.z, acc[6]); acc[7] = fmaf(wa, cur1.w, acc[7]);

        if (final_flag) {
            float* vp = base + (size_t)nn * MD;
            *(float4*)vp       = make_float4(wa * cur0.x, wa * cur0.y, wa * cur0.z, wa * cur0.w);
            *(float4*)(vp + 4) = make_float4(wa * cur1.x, wa * cur1.y, wa * cur1.z, wa * cur1.w);
        }

        cur0 = nxt0; cur1 = nxt1;
    }

    float* co = cap_out + ((size_t)(b * NOUT + m)) * DOUT + j * 8;
    #pragma unroll
    for (int k = 0; k < 8; ++k) atomicAdd(co + k, acc[k]);
}

// ---------------------------------------------------------------------------
__global__ void act_kernel(const float* __restrict__ cap, float* __restrict__ actout)
{
    int i = blockIdx.x * blockDim.x + threadIdx.x;
    if (i < B * NOUT) {
        const float* c = cap + i * DOUT;
        float s = 0.f;
        #pragma unroll
        for (int d = 0; d < DOUT; ++d) s += c[d] * c[d];
        actout[i] = sqrtf(s);
    }
}

// ---------------------------------------------------------------------------
extern "C" void kernel_launch(void* const* d_in, const int* in_sizes, int n_in,
                              void* d_out, int out_size)
{
    const float* pose = (const float*)d_in[0];
    const float* act  = (const float*)d_in[1];
    const float* W    = (const float*)d_in[2];

    float* out = (float*)d_out;
    float* cap = out + OFF_CAP;
    float* qk  = out + OFF_QK;
    float* emb = out + OFF_EMB;

    float* capbuf;
    cudaGetSymbolAddress((void**)&capbuf, g_cap);
    float* cap0 = capbuf;
    float* cap1 = capbuf + B * MD;
    float* cap2 = capbuf + 2 * B * MD;

    cudaFuncSetAttribute(votes_kernel,
                         cudaFuncAttributeMaxDynamicSharedMemorySize, SMEM_V);

    // single zero launch (diagnostic split removed)
    zero_kernel<<<256, 256>>>((float4*)cap0, (float4*)cap);

    votes_kernel<<<dim3(4, 74), 256, SMEM_V>>>(pose, W, emb);

    cap0_kernel<<<dim3(8, B, 2), 256>>>(emb, cap0);

    route_kernel<<<dim3(16, B), 256>>>(emb, act, cap0, cap1, qk, 0);
    route_kernel<<<dim3(16, B), 256>>>(emb, act, cap1, cap2, qk, 0);
    route_kernel<<<dim3(16, B), 256>>>(emb, act, cap2, cap, qk, 1);

    act_kernel<<<4, 256>>>(cap, out + OFF_ACT);
}